// round 1
// baseline (speedup 1.0000x reference)
#include <cuda_runtime.h>
#include <math.h>

#define BATCH    4
#define SEQLEN   4096
#define DIM      1024
#define HEADS    16
#define HEAD_DIM 64
#define SEG      64
#define NSEG     (SEQLEN / SEG)     // 64
#define KSEG     (SEG / 2)          // 32 (dilation 2)
#define KDIM     1024               // GEMM K (reduction) dim, always 1024
#define SCALE    0.125f             // 64^-0.5

// ---------------- scratch (static device globals; no allocs allowed) --------
__device__ float g_Q [BATCH * SEQLEN * DIM];                 // hilbert-ordered Q, [b*L+i][h*64+d]
__device__ float g_KV[BATCH * (SEQLEN / 2) * (2 * DIM)];     // dilated K|V, [b*L/2+m][0:1024 K, 1024:2048 V]
__device__ float g_O [BATCH * SEQLEN * DIM];                 // attention out in ORIGINAL order
__device__ int   g_qrow [BATCH * SEQLEN];
__device__ int   g_kvrow[BATCH * (SEQLEN / 2)];

// ---------------- build gather tables ---------------------------------------
__global__ void build_maps_kernel(const int* __restrict__ hmap) {
    int t = blockIdx.x * blockDim.x + threadIdx.x;
    if (t < BATCH * SEQLEN) {
        int b = t / SEQLEN, i = t % SEQLEN;
        g_qrow[t] = b * SEQLEN + hmap[i];
    }
    if (t < BATCH * (SEQLEN / 2)) {
        int b = t / (SEQLEN / 2), m = t % (SEQLEN / 2);
        int s = m / KSEG, j = m % KSEG;
        g_kvrow[t] = b * SEQLEN + hmap[s * SEG + 2 * j];
    }
}

// ---------------- generic 128x128x16 fp32 GEMM with optional row gather -----
// C[M,N] = A[rowidx[m], 0:1024] @ W[0:1024, n] (W has leading dim ldw)
// M = gridDim.y*128, N = gridDim.x*128, K = 1024. All dims divide evenly.
template <bool GATHER>
__global__ __launch_bounds__(256)
void gemm128_kernel(const float* __restrict__ A,
                    const float* __restrict__ W,
                    float* __restrict__ C,
                    const int* __restrict__ rowidx,
                    int N, int ldw)
{
    __shared__ float As[16][128];   // transposed: As[k][m]
    __shared__ float Bs[16][128];   // Bs[k][n]

    const int tid = threadIdx.x;
    const int bm  = blockIdx.y * 128;
    const int bn  = blockIdx.x * 128;
    const int tx  = tid & 15;       // 0..15 -> 8 cols each
    const int ty  = tid >> 4;       // 0..15 -> 8 rows each

    // A tile: 128 rows x 16 k  = 512 float4 (4 float4 along k per row)
    const int arow0 = tid >> 2;                 // 0..63
    const int ac0   = (tid & 3) * 4;
    const int arow1 = arow0 + 64;
    const int ac1   = ac0;
    long grow0 = GATHER ? (long)rowidx[bm + arow0] : (long)(bm + arow0);
    long grow1 = GATHER ? (long)rowidx[bm + arow1] : (long)(bm + arow1);
    const float* Ap0 = A + grow0 * KDIM + ac0;
    const float* Ap1 = A + grow1 * KDIM + ac1;

    // B tile: 16 k x 128 n = 512 float4 (32 float4 per k-row)
    const int brow0 = tid >> 5;                 // 0..7
    const int bc    = (tid & 31) * 4;
    const int brow1 = brow0 + 8;
    const float* Wp0 = W + (long)brow0 * ldw + bn + bc;
    const float* Wp1 = W + (long)brow1 * ldw + bn + bc;

    float acc[8][8];
#pragma unroll
    for (int i = 0; i < 8; i++)
#pragma unroll
        for (int j = 0; j < 8; j++) acc[i][j] = 0.0f;

    for (int k0 = 0; k0 < KDIM; k0 += 16) {
        float4 av0 = *(const float4*)(Ap0 + k0);
        float4 av1 = *(const float4*)(Ap1 + k0);
        float4 bv0 = *(const float4*)(Wp0 + (long)k0 * ldw);
        float4 bv1 = *(const float4*)(Wp1 + (long)k0 * ldw);

        __syncthreads();
        As[ac0 + 0][arow0] = av0.x; As[ac0 + 1][arow0] = av0.y;
        As[ac0 + 2][arow0] = av0.z; As[ac0 + 3][arow0] = av0.w;
        As[ac1 + 0][arow1] = av1.x; As[ac1 + 1][arow1] = av1.y;
        As[ac1 + 2][arow1] = av1.z; As[ac1 + 3][arow1] = av1.w;
        *(float4*)&Bs[brow0][bc] = bv0;
        *(float4*)&Bs[brow1][bc] = bv1;
        __syncthreads();

#pragma unroll
        for (int k = 0; k < 16; k++) {
            float4 a0 = *(const float4*)&As[k][ty * 8];
            float4 a1 = *(const float4*)&As[k][ty * 8 + 4];
            float4 b0 = *(const float4*)&Bs[k][tx * 8];
            float4 b1 = *(const float4*)&Bs[k][tx * 8 + 4];
            float ar[8] = {a0.x, a0.y, a0.z, a0.w, a1.x, a1.y, a1.z, a1.w};
            float br[8] = {b0.x, b0.y, b0.z, b0.w, b1.x, b1.y, b1.z, b1.w};
#pragma unroll
            for (int i = 0; i < 8; i++)
#pragma unroll
                for (int j = 0; j < 8; j++) acc[i][j] += ar[i] * br[j];
        }
    }

#pragma unroll
    for (int i = 0; i < 8; i++) {
        float* Cp = C + (long)(bm + ty * 8 + i) * N + bn + tx * 8;
        float4 c0 = {acc[i][0], acc[i][1], acc[i][2], acc[i][3]};
        float4 c1 = {acc[i][4], acc[i][5], acc[i][6], acc[i][7]};
        *(float4*)(Cp)     = c0;
        *(float4*)(Cp + 4) = c1;
    }
}

// ---------------- fused segment attention -----------------------------------
// One block per (seg, head, batch). Q tile 64x64, K/V 32x64 (dilated),
// softmax over 32 keys, output scattered back to original sequence order.
__global__ __launch_bounds__(256)
void attn_kernel(const int* __restrict__ hmap)
{
    const int s = blockIdx.x, h = blockIdx.y, b = blockIdx.z;
    __shared__ float Qs[64][65];
    __shared__ float Ks[32][65];
    __shared__ float Vs[32][65];
    __shared__ float Ss[64][33];

    const int tid = threadIdx.x;

    const float* Qbase = g_Q + ((long)(b * SEQLEN + s * SEG)) * DIM + h * HEAD_DIM;
    for (int l = tid; l < 64 * 16; l += 256) {          // float4 granules
        int r = l >> 4, c4 = (l & 15) * 4;
        float4 v = *(const float4*)(Qbase + (long)r * DIM + c4);
        Qs[r][c4] = v.x; Qs[r][c4 + 1] = v.y; Qs[r][c4 + 2] = v.z; Qs[r][c4 + 3] = v.w;
    }
    const float* Kbase = g_KV + ((long)(b * (SEQLEN / 2) + s * KSEG)) * (2 * DIM) + h * HEAD_DIM;
    const float* Vbase = Kbase + DIM;
    for (int l = tid; l < 32 * 16; l += 256) {
        int r = l >> 4, c4 = (l & 15) * 4;
        float4 kv = *(const float4*)(Kbase + (long)r * (2 * DIM) + c4);
        Ks[r][c4] = kv.x; Ks[r][c4 + 1] = kv.y; Ks[r][c4 + 2] = kv.z; Ks[r][c4 + 3] = kv.w;
        float4 vv = *(const float4*)(Vbase + (long)r * (2 * DIM) + c4);
        Vs[r][c4] = vv.x; Vs[r][c4 + 1] = vv.y; Vs[r][c4 + 2] = vv.z; Vs[r][c4 + 3] = vv.w;
    }
    __syncthreads();

    // scores: thread -> row r = tid/4, 8 key-cols starting at (tid%4)*8
    const int r  = tid >> 2;
    const int cg = (tid & 3) * 8;
    {
        float acc[8] = {0, 0, 0, 0, 0, 0, 0, 0};
#pragma unroll 8
        for (int d = 0; d < 64; d++) {
            float qv = Qs[r][d];
#pragma unroll
            for (int c = 0; c < 8; c++) acc[c] += qv * Ks[cg + c][d];
        }
#pragma unroll
        for (int c = 0; c < 8; c++) Ss[r][cg + c] = acc[c] * SCALE;
    }
    __syncthreads();

    if (tid < 64) {
        float mx = -1e30f;
#pragma unroll
        for (int j = 0; j < 32; j++) mx = fmaxf(mx, Ss[tid][j]);
        float sum = 0.0f;
#pragma unroll
        for (int j = 0; j < 32; j++) {
            float e = __expf(Ss[tid][j] - mx);
            Ss[tid][j] = e;
            sum += e;
        }
        float inv = 1.0f / sum;
#pragma unroll
        for (int j = 0; j < 32; j++) Ss[tid][j] *= inv;
    }
    __syncthreads();

    // out = P @ V : thread -> row r, 16 dims starting at (tid%4)*16
    const int dg = (tid & 3) * 16;
    float o[16];
#pragma unroll
    for (int d = 0; d < 16; d++) o[d] = 0.0f;
#pragma unroll 4
    for (int j = 0; j < 32; j++) {
        float p = Ss[r][j];
#pragma unroll
        for (int d = 0; d < 16; d++) o[d] += p * Vs[j][dg + d];
    }

    // scatter to original position (fuses the inverse hilbert permutation)
    const int pos = hmap[s * SEG + r];
    float* Op = g_O + ((long)(b * SEQLEN + pos)) * DIM + h * HEAD_DIM + dg;
#pragma unroll
    for (int d4 = 0; d4 < 16; d4 += 4) {
        float4 v = {o[d4], o[d4 + 1], o[d4 + 2], o[d4 + 3]};
        *(float4*)(Op + d4) = v;
    }
}

// ---------------- launch ------------------------------------------------------
extern "C" void kernel_launch(void* const* d_in, const int* in_sizes, int n_in,
                              void* d_out, int out_size)
{
    const float* x      = (const float*)d_in[0];   // [4,4096,1024]
    const float* w_qkv  = (const float*)d_in[1];   // [1024,3072]
    const float* w_proj = (const float*)d_in[2];   // [1024,1024]
    const int*   hmap   = (const int*)  d_in[3];   // [4096]
    float* out = (float*)d_out;                    // [4,4096,1024]

    float* Q;  cudaGetSymbolAddress((void**)&Q,  g_Q);
    float* KV; cudaGetSymbolAddress((void**)&KV, g_KV);
    float* O;  cudaGetSymbolAddress((void**)&O,  g_O);
    int* qrow;  cudaGetSymbolAddress((void**)&qrow,  g_qrow);
    int* kvrow; cudaGetSymbolAddress((void**)&kvrow, g_kvrow);

    // 1. gather tables
    build_maps_kernel<<<(BATCH * SEQLEN + 255) / 256, 256>>>(hmap);

    // 2. Q = x[qrow] @ Wq           (M=16384, N=1024)
    gemm128_kernel<true><<<dim3(1024 / 128, BATCH * SEQLEN / 128), 256>>>(
        x, w_qkv, Q, qrow, 1024, 3 * DIM);

    // 3. KV = x[kvrow] @ W[k|v]     (M=8192, N=2048) — only dilated rows
    gemm128_kernel<true><<<dim3(2048 / 128, BATCH * (SEQLEN / 2) / 128), 256>>>(
        x, w_qkv + DIM, KV, kvrow, 2048, 3 * DIM);

    // 4. fused segment attention (+ inverse permutation)
    attn_kernel<<<dim3(NSEG, HEADS, BATCH), 256>>>(hmap);

    // 5. out = O @ w_proj           (M=16384, N=1024)
    gemm128_kernel<false><<<dim3(1024 / 128, BATCH * SEQLEN / 128), 256>>>(
        O, w_proj, out, nullptr, 1024, DIM);
}

// round 4
// speedup vs baseline: 3.1373x; 3.1373x over previous
#include <cuda_runtime.h>
#include <cstdint>
#include <math.h>

#define BATCH    4
#define SEQLEN   4096
#define DIM      1024
#define HEADS    16
#define HEAD_DIM 64
#define SEG      64
#define NSEG     (SEQLEN / SEG)     // 64
#define KSEG     (SEG / 2)          // 32 (dilation 2)
#define KDIM     1024               // GEMM reduction dim
#define SCALE    0.125f             // 64^-0.5

// ---------------- scratch (static device globals; no allocs allowed) --------
__device__ float g_Xc[BATCH * SEQLEN * DIM];               // tf32-rounded x
__device__ float g_Q [BATCH * SEQLEN * DIM];               // hilbert-ordered Q
__device__ float g_KV[BATCH * (SEQLEN / 2) * (2 * DIM)];   // dilated K|V
__device__ float g_O [BATCH * SEQLEN * DIM];               // attn out (tf32-rounded)
__device__ float g_WqkvT[3 * DIM * DIM];                   // w_qkv^T, tf32-rounded
__device__ float g_WprojT[DIM * DIM];                      // w_proj^T, tf32-rounded
__device__ int   g_qrow [BATCH * SEQLEN];
__device__ int   g_kvrow[BATCH * (SEQLEN / 2)];

// ---------------- helpers -----------------------------------------------------
__device__ __forceinline__ uint32_t smem_u32(const void* p) {
    uint32_t a;
    asm("{ .reg .u64 t; cvta.to.shared.u64 t, %1; cvt.u32.u64 %0, t; }" : "=r"(a) : "l"(p));
    return a;
}
// tf32 round-to-nearest: PTX cvt.rna.tf32.f32 requires a .b32 destination.
__device__ __forceinline__ float tf32r(float v) {
    uint32_t u;
    asm("cvt.rna.tf32.f32 %0, %1;" : "=r"(u) : "f"(v));
    return __uint_as_float(u);
}
__device__ __forceinline__ float4 tf32x4(float4 v) {
    v.x = tf32r(v.x); v.y = tf32r(v.y); v.z = tf32r(v.z); v.w = tf32r(v.w);
    return v;
}
__device__ __forceinline__ void cp_async16(uint32_t dst, const void* src) {
    asm volatile("cp.async.ca.shared.global [%0], [%1], 16;" :: "r"(dst), "l"(src));
}
__device__ __forceinline__ void cp_commit() {
    asm volatile("cp.async.commit_group;" ::: "memory");
}
template <int N>
__device__ __forceinline__ void cp_wait() {
    asm volatile("cp.async.wait_group %0;" :: "n"(N) : "memory");
}

// ---------------- build gather tables ---------------------------------------
__global__ void build_maps_kernel(const int* __restrict__ hmap) {
    int t = blockIdx.x * blockDim.x + threadIdx.x;
    if (t < BATCH * SEQLEN) {
        int b = t / SEQLEN, i = t % SEQLEN;
        g_qrow[t] = b * SEQLEN + hmap[i];
    }
    if (t < BATCH * (SEQLEN / 2)) {
        int b = t / (SEQLEN / 2), m = t % (SEQLEN / 2);
        int s = m / KSEG, j = m % KSEG;
        g_kvrow[t] = b * SEQLEN + hmap[s * SEG + 2 * j];
    }
}

// ---------------- convert x to tf32-rounded copy -----------------------------
__global__ void convert_x_kernel(const float* __restrict__ x) {
    long t = (long)blockIdx.x * blockDim.x + threadIdx.x;
    float4 v = ((const float4*)x)[t];
    ((float4*)g_Xc)[t] = tf32x4(v);
}

// ---------------- weight transpose + tf32 round ------------------------------
__global__ void transpose_kernel(const float* __restrict__ W, float* __restrict__ Wt,
                                 int rows, int cols) {  // W[rows][cols] -> Wt[cols][rows]
    __shared__ float t[32][33];
    int bx = blockIdx.x * 32, by = blockIdx.y * 32;
#pragma unroll
    for (int i = 0; i < 32; i += 8) {
        int y = by + threadIdx.y + i, x = bx + threadIdx.x;
        t[threadIdx.y + i][threadIdx.x] = W[(long)y * cols + x];
    }
    __syncthreads();
#pragma unroll
    for (int i = 0; i < 32; i += 8) {
        int y = bx + threadIdx.y + i, x = by + threadIdx.x;
        Wt[(long)y * rows + x] = tf32r(t[threadIdx.x][threadIdx.y + i]);
    }
}

// ---------------- tf32 mma.sync GEMM -----------------------------------------
// C[M,N] = A[rowid[m], :] @ Bt[n, :]^T. Tile 128x128, K-chunk 32, 2-stage cp.async.
// smem per stage: A[128][36] + B[128][36] floats (pad 36 -> conflict-free frags)
#define PAD      36
#define TILE_F   (128 * PAD)                  // floats per array
#define STAGE_BYTES (2 * TILE_F * 4)          // A + B = 36864

extern __shared__ __align__(16) char dynsmem[];

__global__ __launch_bounds__(256, 2)
void gemm_mma_kernel(const float* __restrict__ A, const float* __restrict__ Bt,
                     float* __restrict__ C, const int* __restrict__ rowidx, int ldc)
{
    __shared__ int rowid[128];

    const int tid   = threadIdx.x;
    const int wid   = tid >> 5;
    const int lane  = tid & 31;
    const int gid   = lane >> 2;      // 0..7
    const int tidg  = lane & 3;       // 0..3
    const int warp_m = wid >> 2;      // 0..1
    const int warp_n = wid & 3;       // 0..3
    const int bm = blockIdx.y * 128;
    const int bn = blockIdx.x * 128;

    if (tid < 128) rowid[tid] = rowidx ? rowidx[bm + tid] : (bm + tid);
    __syncthreads();

    const uint32_t smb = smem_u32(dynsmem);

    // ---- cp.async issue for one K-chunk into stage s ----
    auto issue = [&](int chunk, int s) {
        const int koff = chunk * 32;
        const uint32_t sA = smb + s * STAGE_BYTES;
        const uint32_t sB = sA + TILE_F * 4;
#pragma unroll
        for (int i = 0; i < 4; i++) {
            int idx = tid + i * 256;          // 0..1023
            int row = idx >> 3, c = idx & 7;
            cp_async16(sA + (row * PAD + c * 4) * 4,
                       A + (long)rowid[row] * KDIM + koff + c * 4);
        }
#pragma unroll
        for (int i = 0; i < 4; i++) {
            int idx = tid + i * 256;
            int row = idx >> 3, c = idx & 7;
            cp_async16(sB + (row * PAD + c * 4) * 4,
                       Bt + (long)(bn + row) * KDIM + koff + c * 4);
        }
        cp_commit();
    };

    float acc[4][4][4];
#pragma unroll
    for (int i = 0; i < 4; i++)
#pragma unroll
        for (int j = 0; j < 4; j++)
#pragma unroll
            for (int r = 0; r < 4; r++) acc[i][j][r] = 0.0f;

    issue(0, 0);

    for (int c = 0; c < KDIM / 32; ++c) {
        if (c + 1 < KDIM / 32) { issue(c + 1, (c + 1) & 1); cp_wait<1>(); }
        else                   { cp_wait<0>(); }
        __syncthreads();

        const uint32_t* As = (const uint32_t*)(dynsmem + (c & 1) * STAGE_BYTES);
        const uint32_t* Bs = As + TILE_F;

#pragma unroll
        for (int ks = 0; ks < 4; ++ks) {
            const int k0 = ks * 8;
            uint32_t af[4][4], bf[4][2];
#pragma unroll
            for (int mt = 0; mt < 4; ++mt) {
                int r = warp_m * 64 + mt * 16 + gid;
                af[mt][0] = As[r * PAD + k0 + tidg];
                af[mt][1] = As[(r + 8) * PAD + k0 + tidg];
                af[mt][2] = As[r * PAD + k0 + tidg + 4];
                af[mt][3] = As[(r + 8) * PAD + k0 + tidg + 4];
            }
#pragma unroll
            for (int nt = 0; nt < 4; ++nt) {
                int rn = warp_n * 32 + nt * 8 + gid;
                bf[nt][0] = Bs[rn * PAD + k0 + tidg];
                bf[nt][1] = Bs[rn * PAD + k0 + tidg + 4];
            }
#pragma unroll
            for (int mt = 0; mt < 4; ++mt)
#pragma unroll
                for (int nt = 0; nt < 4; ++nt) {
                    asm volatile(
                        "mma.sync.aligned.m16n8k8.row.col.f32.tf32.tf32.f32 "
                        "{%0,%1,%2,%3}, {%4,%5,%6,%7}, {%8,%9}, {%0,%1,%2,%3};"
                        : "+f"(acc[mt][nt][0]), "+f"(acc[mt][nt][1]),
                          "+f"(acc[mt][nt][2]), "+f"(acc[mt][nt][3])
                        : "r"(af[mt][0]), "r"(af[mt][1]), "r"(af[mt][2]), "r"(af[mt][3]),
                          "r"(bf[nt][0]), "r"(bf[nt][1]));
                }
        }
        __syncthreads();
    }

    // ---- epilogue ----
#pragma unroll
    for (int mt = 0; mt < 4; ++mt) {
        const int row0 = bm + warp_m * 64 + mt * 16 + gid;
#pragma unroll
        for (int nt = 0; nt < 4; ++nt) {
            const int col = bn + warp_n * 32 + nt * 8 + tidg * 2;
            float2 v0 = {acc[mt][nt][0], acc[mt][nt][1]};
            float2 v1 = {acc[mt][nt][2], acc[mt][nt][3]};
            *(float2*)(C + (long)row0 * ldc + col)       = v0;
            *(float2*)(C + (long)(row0 + 8) * ldc + col) = v1;
        }
    }
}

// ---------------- fused segment attention (fp32, tf32-rounded output) --------
__global__ __launch_bounds__(256)
void attn_kernel(const int* __restrict__ hmap)
{
    const int s = blockIdx.x, h = blockIdx.y, b = blockIdx.z;
    __shared__ float Qs[64][65];
    __shared__ float Ks[32][65];
    __shared__ float Vs[32][65];
    __shared__ float Ss[64][33];

    const int tid = threadIdx.x;

    const float* Qbase = g_Q + ((long)(b * SEQLEN + s * SEG)) * DIM + h * HEAD_DIM;
    for (int l = tid; l < 64 * 16; l += 256) {
        int r = l >> 4, c4 = (l & 15) * 4;
        float4 v = *(const float4*)(Qbase + (long)r * DIM + c4);
        Qs[r][c4] = v.x; Qs[r][c4 + 1] = v.y; Qs[r][c4 + 2] = v.z; Qs[r][c4 + 3] = v.w;
    }
    const float* Kbase = g_KV + ((long)(b * (SEQLEN / 2) + s * KSEG)) * (2 * DIM) + h * HEAD_DIM;
    const float* Vbase = Kbase + DIM;
    for (int l = tid; l < 32 * 16; l += 256) {
        int r = l >> 4, c4 = (l & 15) * 4;
        float4 kv = *(const float4*)(Kbase + (long)r * (2 * DIM) + c4);
        Ks[r][c4] = kv.x; Ks[r][c4 + 1] = kv.y; Ks[r][c4 + 2] = kv.z; Ks[r][c4 + 3] = kv.w;
        float4 vv = *(const float4*)(Vbase + (long)r * (2 * DIM) + c4);
        Vs[r][c4] = vv.x; Vs[r][c4 + 1] = vv.y; Vs[r][c4 + 2] = vv.z; Vs[r][c4 + 3] = vv.w;
    }
    __syncthreads();

    const int r  = tid >> 2;
    const int cg = (tid & 3) * 8;
    {
        float acc[8] = {0, 0, 0, 0, 0, 0, 0, 0};
#pragma unroll 8
        for (int d = 0; d < 64; d++) {
            float qv = Qs[r][d];
#pragma unroll
            for (int c = 0; c < 8; c++) acc[c] += qv * Ks[cg + c][d];
        }
#pragma unroll
        for (int c = 0; c < 8; c++) Ss[r][cg + c] = acc[c] * SCALE;
    }
    __syncthreads();

    if (tid < 64) {
        float mx = -1e30f;
#pragma unroll
        for (int j = 0; j < 32; j++) mx = fmaxf(mx, Ss[tid][j]);
        float sum = 0.0f;
#pragma unroll
        for (int j = 0; j < 32; j++) {
            float e = __expf(Ss[tid][j] - mx);
            Ss[tid][j] = e;
            sum += e;
        }
        float inv = 1.0f / sum;
#pragma unroll
        for (int j = 0; j < 32; j++) Ss[tid][j] *= inv;
    }
    __syncthreads();

    const int dg = (tid & 3) * 16;
    float o[16];
#pragma unroll
    for (int d = 0; d < 16; d++) o[d] = 0.0f;
#pragma unroll 4
    for (int j = 0; j < 32; j++) {
        float p = Ss[r][j];
#pragma unroll
        for (int d = 0; d < 16; d++) o[d] += p * Vs[j][dg + d];
    }

    const int pos = hmap[s * SEG + r];
    float* Op = g_O + ((long)(b * SEQLEN + pos)) * DIM + h * HEAD_DIM + dg;
#pragma unroll
    for (int d4 = 0; d4 < 16; d4 += 4) {
        float4 v = {tf32r(o[d4]), tf32r(o[d4 + 1]), tf32r(o[d4 + 2]), tf32r(o[d4 + 3])};
        *(float4*)(Op + d4) = v;
    }
}

// ---------------- launch ------------------------------------------------------
extern "C" void kernel_launch(void* const* d_in, const int* in_sizes, int n_in,
                              void* d_out, int out_size)
{
    const float* x      = (const float*)d_in[0];   // [4,4096,1024]
    const float* w_qkv  = (const float*)d_in[1];   // [1024,3072]
    const float* w_proj = (const float*)d_in[2];   // [1024,1024]
    const int*   hmap   = (const int*)  d_in[3];   // [4096]
    float* out = (float*)d_out;                    // [4,4096,1024]

    float* Xc;  cudaGetSymbolAddress((void**)&Xc,  g_Xc);
    float* Q;   cudaGetSymbolAddress((void**)&Q,   g_Q);
    float* KV;  cudaGetSymbolAddress((void**)&KV,  g_KV);
    float* O;   cudaGetSymbolAddress((void**)&O,   g_O);
    float* WqT; cudaGetSymbolAddress((void**)&WqT, g_WqkvT);
    float* WpT; cudaGetSymbolAddress((void**)&WpT, g_WprojT);
    int* qrow;  cudaGetSymbolAddress((void**)&qrow,  g_qrow);
    int* kvrow; cudaGetSymbolAddress((void**)&kvrow, g_kvrow);

    static bool attr_done = false;
    if (!attr_done) {
        cudaFuncSetAttribute(gemm_mma_kernel, cudaFuncAttributeMaxDynamicSharedMemorySize,
                             STAGE_BYTES * 2);
        attr_done = true;
    }

    // 1. tables + tf32 pre-rounding
    build_maps_kernel<<<(BATCH * SEQLEN + 255) / 256, 256>>>(hmap);
    convert_x_kernel<<<(BATCH * SEQLEN * DIM / 4) / 256, 256>>>(x);
    transpose_kernel<<<dim3(3 * DIM / 32, DIM / 32), dim3(32, 8)>>>(w_qkv, WqT, DIM, 3 * DIM);
    transpose_kernel<<<dim3(DIM / 32, DIM / 32), dim3(32, 8)>>>(w_proj, WpT, DIM, DIM);

    // 2. Q = x[qrow] @ Wq          (M=16384, N=1024)
    gemm_mma_kernel<<<dim3(1024 / 128, BATCH * SEQLEN / 128), 256, STAGE_BYTES * 2>>>(
        Xc, WqT, Q, qrow, 1024);

    // 3. KV = x[kvrow] @ W[k|v]    (M=8192, N=2048)
    gemm_mma_kernel<<<dim3(2048 / 128, BATCH * (SEQLEN / 2) / 128), 256, STAGE_BYTES * 2>>>(
        Xc, WqT + (long)DIM * DIM, KV, kvrow, 2048);

    // 4. fused segment attention (+ inverse permutation)
    attn_kernel<<<dim3(NSEG, HEADS, BATCH), 256>>>(hmap);

    // 5. out = O @ w_proj          (M=16384, N=1024)
    gemm_mma_kernel<<<dim3(1024 / 128, BATCH * SEQLEN / 128), 256, STAGE_BYTES * 2>>>(
        O, WpT, out, nullptr, 1024);
}

// round 5
// speedup vs baseline: 3.3210x; 1.0586x over previous
#include <cuda_runtime.h>
#include <cstdint>
#include <math.h>

#define BATCH    4
#define SEQLEN   4096
#define DIM      1024
#define HEADS    16
#define HEAD_DIM 64
#define SEG      64
#define NSEG     (SEQLEN / SEG)     // 64
#define KSEG     (SEG / 2)          // 32 (dilation 2)
#define KDIM     1024               // GEMM reduction dim
#define SCALE    0.125f             // 64^-0.5

// ---------------- scratch (static device globals; no allocs allowed) --------
__device__ float g_Xc[BATCH * SEQLEN * DIM];               // tf32-rounded x
__device__ float g_Q [BATCH * SEQLEN * DIM];               // hilbert-ordered Q
__device__ float g_KV[BATCH * (SEQLEN / 2) * (2 * DIM)];   // dilated K|V
__device__ float g_O [BATCH * SEQLEN * DIM];               // attn out (tf32-rounded)
__device__ float g_WqkvT[3 * DIM * DIM];                   // w_qkv^T, tf32-rounded
__device__ float g_WprojT[DIM * DIM];                      // w_proj^T, tf32-rounded
__device__ int   g_qrow [BATCH * SEQLEN];
__device__ int   g_kvrow[BATCH * (SEQLEN / 2)];

// ---------------- helpers -----------------------------------------------------
__device__ __forceinline__ uint32_t smem_u32(const void* p) {
    uint32_t a;
    asm("{ .reg .u64 t; cvta.to.shared.u64 t, %1; cvt.u32.u64 %0, t; }" : "=r"(a) : "l"(p));
    return a;
}
__device__ __forceinline__ float tf32r(float v) {
    uint32_t u;
    asm("cvt.rna.tf32.f32 %0, %1;" : "=r"(u) : "f"(v));
    return __uint_as_float(u);
}
__device__ __forceinline__ float4 tf32x4(float4 v) {
    v.x = tf32r(v.x); v.y = tf32r(v.y); v.z = tf32r(v.z); v.w = tf32r(v.w);
    return v;
}
__device__ __forceinline__ void cp_async16(uint32_t dst, const void* src) {
    asm volatile("cp.async.ca.shared.global [%0], [%1], 16;" :: "r"(dst), "l"(src));
}
__device__ __forceinline__ void cp_commit() {
    asm volatile("cp.async.commit_group;" ::: "memory");
}
template <int N>
__device__ __forceinline__ void cp_wait() {
    asm volatile("cp.async.wait_group %0;" :: "n"(N) : "memory");
}

// ---------------- build gather tables ---------------------------------------
__global__ void build_maps_kernel(const int* __restrict__ hmap) {
    int t = blockIdx.x * blockDim.x + threadIdx.x;
    if (t < BATCH * SEQLEN) {
        int b = t / SEQLEN, i = t % SEQLEN;
        g_qrow[t] = b * SEQLEN + hmap[i];
    }
    if (t < BATCH * (SEQLEN / 2)) {
        int b = t / (SEQLEN / 2), m = t % (SEQLEN / 2);
        int s = m / KSEG, j = m % KSEG;
        g_kvrow[t] = b * SEQLEN + hmap[s * SEG + 2 * j];
    }
}

// ---------------- convert x to tf32-rounded copy -----------------------------
__global__ void convert_x_kernel(const float* __restrict__ x) {
    long t = (long)blockIdx.x * blockDim.x + threadIdx.x;
    float4 v = ((const float4*)x)[t];
    ((float4*)g_Xc)[t] = tf32x4(v);
}

// ---------------- weight transpose + tf32 round ------------------------------
__global__ void transpose_kernel(const float* __restrict__ W, float* __restrict__ Wt,
                                 int rows, int cols) {  // W[rows][cols] -> Wt[cols][rows]
    __shared__ float t[32][33];
    int bx = blockIdx.x * 32, by = blockIdx.y * 32;
#pragma unroll
    for (int i = 0; i < 32; i += 8) {
        int y = by + threadIdx.y + i, x = bx + threadIdx.x;
        t[threadIdx.y + i][threadIdx.x] = W[(long)y * cols + x];
    }
    __syncthreads();
#pragma unroll
    for (int i = 0; i < 32; i += 8) {
        int y = bx + threadIdx.y + i, x = by + threadIdx.x;
        Wt[(long)y * rows + x] = tf32r(t[threadIdx.x][threadIdx.y + i]);
    }
}

// ---------------- tf32 mma.sync GEMM -----------------------------------------
// C[M,N] = A[rowid[m], :] @ Bt[n, :]^T. Tile 128x128, 4 warps of 64x64 each,
// K-chunk 32, 3-stage cp.async ring with a single barrier per chunk.
#define PAD      36
#define TILE_F   (128 * PAD)                  // floats per array
#define STAGE_BYTES (2 * TILE_F * 4)          // A + B = 36864
#define NSTAGE   3
#define GSMEM    (NSTAGE * STAGE_BYTES)       // 110592

extern __shared__ __align__(16) char dynsmem[];

__global__ __launch_bounds__(128, 2)
void gemm_mma_kernel(const float* __restrict__ A, const float* __restrict__ Bt,
                     float* __restrict__ C, const int* __restrict__ rowidx, int ldc)
{
    __shared__ int rowid[128];

    const int tid   = threadIdx.x;
    const int wid   = tid >> 5;       // 0..3
    const int lane  = tid & 31;
    const int gid   = lane >> 2;      // 0..7
    const int tidg  = lane & 3;       // 0..3
    const int warp_m = wid >> 1;      // 0..1
    const int warp_n = wid & 1;       // 0..1
    const int bm = blockIdx.y * 128;
    const int bn = blockIdx.x * 128;

    if (tid < 128) rowid[tid] = rowidx ? rowidx[bm + tid] : (bm + tid);
    __syncthreads();

    const uint32_t smb = smem_u32(dynsmem);

    auto issue = [&](int chunk) {
        const int s = chunk % NSTAGE;
        const int koff = chunk * 32;
        const uint32_t sA = smb + s * STAGE_BYTES;
        const uint32_t sB = sA + TILE_F * 4;
#pragma unroll
        for (int i = 0; i < 8; i++) {
            int idx = tid + i * 128;          // 0..1023
            int row = idx >> 3, c = idx & 7;
            cp_async16(sA + (row * PAD + c * 4) * 4,
                       A + (long)rowid[row] * KDIM + koff + c * 4);
        }
#pragma unroll
        for (int i = 0; i < 8; i++) {
            int idx = tid + i * 128;
            int row = idx >> 3, c = idx & 7;
            cp_async16(sB + (row * PAD + c * 4) * 4,
                       Bt + (long)(bn + row) * KDIM + koff + c * 4);
        }
        cp_commit();
    };

    float acc[4][8][4];
#pragma unroll
    for (int i = 0; i < 4; i++)
#pragma unroll
        for (int j = 0; j < 8; j++)
#pragma unroll
            for (int r = 0; r < 4; r++) acc[i][j][r] = 0.0f;

    issue(0);
    issue(1);

    for (int c = 0; c < KDIM / 32; ++c) {
        if (c < KDIM / 32 - 1) cp_wait<1>();   // chunk c landed
        else                   cp_wait<0>();
        __syncthreads();                        // all warps done reading stage (c+2)%3
        if (c + 2 < KDIM / 32) issue(c + 2);

        const uint32_t* As = (const uint32_t*)(dynsmem + (c % NSTAGE) * STAGE_BYTES);
        const uint32_t* Bs = As + TILE_F;

#pragma unroll
        for (int ks = 0; ks < 4; ++ks) {
            const int k0 = ks * 8;
            uint32_t af[4][4], bf[8][2];
#pragma unroll
            for (int mt = 0; mt < 4; ++mt) {
                int r = warp_m * 64 + mt * 16 + gid;
                af[mt][0] = As[r * PAD + k0 + tidg];
                af[mt][1] = As[(r + 8) * PAD + k0 + tidg];
                af[mt][2] = As[r * PAD + k0 + tidg + 4];
                af[mt][3] = As[(r + 8) * PAD + k0 + tidg + 4];
            }
#pragma unroll
            for (int nt = 0; nt < 8; ++nt) {
                int rn = warp_n * 64 + nt * 8 + gid;
                bf[nt][0] = Bs[rn * PAD + k0 + tidg];
                bf[nt][1] = Bs[rn * PAD + k0 + tidg + 4];
            }
#pragma unroll
            for (int mt = 0; mt < 4; ++mt)
#pragma unroll
                for (int nt = 0; nt < 8; ++nt) {
                    asm volatile(
                        "mma.sync.aligned.m16n8k8.row.col.f32.tf32.tf32.f32 "
                        "{%0,%1,%2,%3}, {%4,%5,%6,%7}, {%8,%9}, {%0,%1,%2,%3};"
                        : "+f"(acc[mt][nt][0]), "+f"(acc[mt][nt][1]),
                          "+f"(acc[mt][nt][2]), "+f"(acc[mt][nt][3])
                        : "r"(af[mt][0]), "r"(af[mt][1]), "r"(af[mt][2]), "r"(af[mt][3]),
                          "r"(bf[nt][0]), "r"(bf[nt][1]));
                }
        }
    }

    // ---- epilogue ----
#pragma unroll
    for (int mt = 0; mt < 4; ++mt) {
        const int row0 = bm + warp_m * 64 + mt * 16 + gid;
#pragma unroll
        for (int nt = 0; nt < 8; ++nt) {
            const int col = bn + warp_n * 64 + nt * 8 + tidg * 2;
            float2 v0 = {acc[mt][nt][0], acc[mt][nt][1]};
            float2 v1 = {acc[mt][nt][2], acc[mt][nt][3]};
            *(float2*)(C + (long)row0 * ldc + col)       = v0;
            *(float2*)(C + (long)(row0 + 8) * ldc + col) = v1;
        }
    }
}

// ---------------- fused segment attention (fp32, vectorized smem) ------------
// K is stored with a 16B-granule XOR swizzle (granule ^= (row>>3)&3) so the
// score loop's 4 key-rows {c, c+8, c+16, c+24} hit distinct bank groups.
__global__ __launch_bounds__(256)
void attn_kernel(const int* __restrict__ hmap)
{
    const int s = blockIdx.x, h = blockIdx.y, b = blockIdx.z;
    __shared__ float Qs[64][68];
    __shared__ float Ks[32][68];
    __shared__ float Vs[32][68];
    __shared__ float Ss[64][33];

    const int tid = threadIdx.x;

    const float* Qbase = g_Q + ((long)(b * SEQLEN + s * SEG)) * DIM + h * HEAD_DIM;
    for (int l = tid; l < 64 * 16; l += 256) {
        int r = l >> 4, g = l & 15;
        *(float4*)&Qs[r][g * 4] = *(const float4*)(Qbase + (long)r * DIM + g * 4);
    }
    const float* Kbase = g_KV + ((long)(b * (SEQLEN / 2) + s * KSEG)) * (2 * DIM) + h * HEAD_DIM;
    const float* Vbase = Kbase + DIM;
    for (int l = tid; l < 32 * 16; l += 256) {
        int r = l >> 4, g = l & 15;
        int gp = g ^ ((r >> 3) & 3);                       // K swizzle
        *(float4*)&Ks[r][gp * 4] = *(const float4*)(Kbase + (long)r * (2 * DIM) + g * 4);
        *(float4*)&Vs[r][g * 4]  = *(const float4*)(Vbase + (long)r * (2 * DIM) + g * 4);
    }
    __syncthreads();

    // ---- scores: thread -> (q-row r, key-group cg of 8) ----
    const int r  = tid >> 2;
    const int cg = (tid & 3) * 8;
    {
        float acc[8] = {0, 0, 0, 0, 0, 0, 0, 0};
#pragma unroll
        for (int gd = 0; gd < 16; ++gd) {
            float4 q = *(const float4*)&Qs[r][gd * 4];
#pragma unroll
            for (int cc = 0; cc < 8; ++cc) {
                const int row = cg + cc;
                float4 kv = *(const float4*)&Ks[row][(gd ^ ((row >> 3) & 3)) * 4];
                acc[cc] += q.x * kv.x + q.y * kv.y + q.z * kv.z + q.w * kv.w;
            }
        }
#pragma unroll
        for (int cc = 0; cc < 8; ++cc) Ss[r][cg + cc] = acc[cc] * SCALE;
    }
    __syncthreads();

    // ---- softmax over 32 keys ----
    if (tid < 64) {
        float mx = -1e30f;
#pragma unroll
        for (int j = 0; j < 32; j++) mx = fmaxf(mx, Ss[tid][j]);
        float sum = 0.0f;
#pragma unroll
        for (int j = 0; j < 32; j++) {
            float e = __expf(Ss[tid][j] - mx);
            Ss[tid][j] = e;
            sum += e;
        }
        float inv = 1.0f / sum;
#pragma unroll
        for (int j = 0; j < 32; j++) Ss[tid][j] *= inv;
    }
    __syncthreads();

    // ---- out = P @ V : thread -> (row r, 4 strided 16B granules t4) ----
    const int t4 = tid & 3;
    float4 o[4];
#pragma unroll
    for (int k = 0; k < 4; k++) o[k] = make_float4(0.f, 0.f, 0.f, 0.f);
#pragma unroll 4
    for (int j = 0; j < 32; j++) {
        float p = Ss[r][j];
#pragma unroll
        for (int k = 0; k < 4; k++) {
            float4 v = *(const float4*)&Vs[j][k * 16 + t4 * 4];
            o[k].x += p * v.x; o[k].y += p * v.y; o[k].z += p * v.z; o[k].w += p * v.w;
        }
    }

    const int pos = hmap[s * SEG + r];
    float* Op = g_O + ((long)(b * SEQLEN + pos)) * DIM + h * HEAD_DIM;
#pragma unroll
    for (int k = 0; k < 4; k++)
        *(float4*)(Op + k * 16 + t4 * 4) = tf32x4(o[k]);
}

// ---------------- launch ------------------------------------------------------
extern "C" void kernel_launch(void* const* d_in, const int* in_sizes, int n_in,
                              void* d_out, int out_size)
{
    const float* x      = (const float*)d_in[0];   // [4,4096,1024]
    const float* w_qkv  = (const float*)d_in[1];   // [1024,3072]
    const float* w_proj = (const float*)d_in[2];   // [1024,1024]
    const int*   hmap   = (const int*)  d_in[3];   // [4096]
    float* out = (float*)d_out;                    // [4,4096,1024]

    float* Xc;  cudaGetSymbolAddress((void**)&Xc,  g_Xc);
    float* Q;   cudaGetSymbolAddress((void**)&Q,   g_Q);
    float* KV;  cudaGetSymbolAddress((void**)&KV,  g_KV);
    float* O;   cudaGetSymbolAddress((void**)&O,   g_O);
    float* WqT; cudaGetSymbolAddress((void**)&WqT, g_WqkvT);
    float* WpT; cudaGetSymbolAddress((void**)&WpT, g_WprojT);
    int* qrow;  cudaGetSymbolAddress((void**)&qrow,  g_qrow);
    int* kvrow; cudaGetSymbolAddress((void**)&kvrow, g_kvrow);

    static bool attr_done = false;
    if (!attr_done) {
        cudaFuncSetAttribute(gemm_mma_kernel, cudaFuncAttributeMaxDynamicSharedMemorySize,
                             GSMEM);
        attr_done = true;
    }

    // 1. tables + tf32 pre-rounding
    build_maps_kernel<<<(BATCH * SEQLEN + 255) / 256, 256>>>(hmap);
    convert_x_kernel<<<(BATCH * SEQLEN * DIM / 4) / 256, 256>>>(x);
    transpose_kernel<<<dim3(3 * DIM / 32, DIM / 32), dim3(32, 8)>>>(w_qkv, WqT, DIM, 3 * DIM);
    transpose_kernel<<<dim3(DIM / 32, DIM / 32), dim3(32, 8)>>>(w_proj, WpT, DIM, DIM);

    // 2. Q = x[qrow] @ Wq          (M=16384, N=1024)
    gemm_mma_kernel<<<dim3(1024 / 128, BATCH * SEQLEN / 128), 128, GSMEM>>>(
        Xc, WqT, Q, qrow, 1024);

    // 3. KV = x[kvrow] @ W[k|v]    (M=8192, N=2048)
    gemm_mma_kernel<<<dim3(2048 / 128, BATCH * (SEQLEN / 2) / 128), 128, GSMEM>>>(
        Xc, WqT + (long)DIM * DIM, KV, kvrow, 2048);

    // 4. fused segment attention (+ inverse permutation)
    attn_kernel<<<dim3(NSEG, HEADS, BATCH), 256>>>(hmap);

    // 5. out = O @ w_proj          (M=16384, N=1024)
    gemm_mma_kernel<<<dim3(1024 / 128, BATCH * SEQLEN / 128), 128, GSMEM>>>(
        O, WpT, out, nullptr, 1024);
}